// round 13
// baseline (speedup 1.0000x reference)
#include <cuda_runtime.h>
#include <cuda_bf16.h>
#include <math.h>

#define MAXN   8192
#define FDIM   128
#define HDIM   64
#define NB     48
#define TA     32        // atoms per feature block (four 8-atom halves)
#define MAXSEG 320       // max atoms per molecule (mean 128, sd ~11)
#define SPLIT  32        // blocks per molecule in pair kernel
#define QSCALE 3.7946016f   // sqrt(14.399)

// ---------------- device scratch (zero-init; reset by features blk 0) -------
__device__ double g_energy;
__device__ int    g_done;
__device__ int    g_start[NB];
__device__ int    g_end[NB];
__device__ __align__(16) float g_p1[MAXN * 4];   // {x, y, z, q*QSCALE}
__device__ __align__(16) float g_p2[MAXN * 4];   // {mux, muy, muz, sqrt_c6}

// ---------------- f32x2 helpers ---------------------------------------------
__device__ __forceinline__ unsigned long long pack2(float lo, float hi) {
    unsigned long long r;
    asm("mov.b64 %0, {%1, %2};" : "=l"(r) : "f"(lo), "f"(hi));
    return r;
}
__device__ __forceinline__ void unpack2(unsigned long long v, float& lo, float& hi) {
    asm("mov.b64 {%0, %1}, %2;" : "=f"(lo), "=f"(hi) : "l"(v));
}
__device__ __forceinline__ void ffma2(unsigned long long& d, unsigned long long a,
                                      unsigned long long b, unsigned long long c) {
    asm("fma.rn.f32x2 %0, %1, %2, %3;" : "=l"(d) : "l"(a), "l"(b), "l"(c));
}
__device__ __forceinline__ void lds_v2_u64(unsigned long long& a, unsigned long long& b,
                                           unsigned int smem_addr) {
    asm("ld.shared.v2.u64 {%0, %1}, [%2];" : "=l"(a), "=l"(b) : "r"(smem_addr));
}

// ================= features =================================================
// 512 threads = four independent 128-thread halves; each half: 8 atoms,
// thread ht: hidden unit ht&63 of MLP ht>>6. 192 blocks -> weight re-read
// traffic 12 MB (each SM's halves share L1 for the weight stream).
__global__ __launch_bounds__(512) void features_kernel(
    const float* __restrict__ h0, const float* __restrict__ h1,
    const float* __restrict__ pos, const int* __restrict__ batch,
    const float* __restrict__ qW1, const float* __restrict__ qb1,
    const float* __restrict__ qW2, const float* __restrict__ qb2,
    const float* __restrict__ cW1, const float* __restrict__ cb1,
    const float* __restrict__ cW2, const float* __restrict__ cb2,
    const float* __restrict__ muW, int N)
{
    int t    = threadIdx.x;          // 0..511
    int half = t >> 7;               // 0..3
    int ht   = t & 127;
    int a0   = blockIdx.x * TA;      // block's first atom
    int a0h  = a0 + half * 8;        // this half's first atom

    if (blockIdx.x == 0 && t == 0) { g_energy = 0.0; g_done = 0; }

    __shared__ __align__(16) float h0s[TA][FDIM];    // 16 KB
    __shared__ float part[16][8];                    // [warp][atom-in-half]

    int warp = t >> 5, lane = t & 31;

    // prefetch pos for this half's atom ht (same thread writes g_p1 later)
    float px = 0.f, py = 0.f, pz = 0.f;
    if (ht < 8) {
        px = pos[(a0h + ht) * 3 + 0];
        py = pos[(a0h + ht) * 3 + 1];
        pz = pos[(a0h + ht) * 3 + 2];
    }

    // stage h0 tile: 1024 float4, 512 threads -> 2 each (coalesced)
    {
        const float4* src = (const float4*)(h0 + (size_t)a0 * FDIM);
        float4* dst = (float4*)&h0s[0][0];
        dst[t]       = src[t];
        dst[t + 512] = src[t + 512];
    }

    // segment boundary detection (batch is sorted)
    if (t < TA) {
        int i  = a0 + t;
        int bi = batch[i];
        if (i == 0 || batch[i - 1] != bi) g_start[bi] = i;
        if (i == N - 1 || batch[i + 1] != bi) g_end[bi] = i + 1;
    }
    __syncthreads();

    int mlp = ht >> 6;          // 0 = q, 1 = c
    int hu  = ht & 63;
    const float* W1 = mlp ? cW1 : qW1;
    const float* B1 = mlp ? cb1 : qb1;
    const float* W2 = mlp ? cW2 : qW2;

    unsigned int hbase = (unsigned int)__cvta_generic_to_shared(&h0s[0][0])
                       + half * 8 * (FDIM * 4);

    unsigned long long acc[8];
    #pragma unroll
    for (int a = 0; a < 8; a++) acc[a] = 0ull;

    #pragma unroll 4
    for (int f0 = 0; f0 < FDIM; f0 += 4) {
        const float* wp = W1 + f0 * HDIM + hu;
        float wa = wp[0];
        float wb = wp[HDIM];
        float wc = wp[2 * HDIM];
        float wd = wp[3 * HDIM];
        unsigned long long w01 = pack2(wa, wb);
        unsigned long long w23 = pack2(wc, wd);
        unsigned int addr = hbase + f0 * 4;
        #pragma unroll
        for (int a = 0; a < 8; a++) {
            unsigned long long hA, hB;
            lds_v2_u64(hA, hB, addr + a * (FDIM * 4));   // uniform -> broadcast
            ffma2(acc[a], hA, w01, acc[a]);
            ffma2(acc[a], hB, w23, acc[a]);
        }
    }

    // epilogue: silu * W2, then 8 INTERLEAVED shuffle-reduce chains
    float b1v = B1[hu];
    float w2v = W2[hu];
    float v[8];
    #pragma unroll
    for (int a = 0; a < 8; a++) {
        float p0, p1;
        unpack2(acc[a], p0, p1);
        float pre = p0 + p1 + b1v;
        v[a] = (pre / (1.0f + __expf(-pre))) * w2v;
    }
    #pragma unroll
    for (int off = 16; off >= 1; off >>= 1) {
        #pragma unroll
        for (int a = 0; a < 8; a++)
            v[a] += __shfl_xor_sync(0xffffffffu, v[a], off);
    }
    if (lane == 0) {
        #pragma unroll
        for (int a = 0; a < 8; a++) part[warp][a] = v[a];
    }
    __syncthreads();

    if (ht < 16) {
        int m2 = ht >> 3, a = ht & 7;    // m2: 0=q, 1=c
        float sum = part[half * 4 + 2 * m2][a] + part[half * 4 + 2 * m2 + 1][a];
        if (m2 == 0) {
            // ht == a here, so px/py/pz belong to atom a0h + a
            float qs = (sum + qb2[0]) * QSCALE;
            ((float4*)g_p1)[a0h + a] = make_float4(px, py, pz, qs);
        } else {
            float c_raw = sum + cb2[0];
            float sp = (c_raw > 20.0f) ? c_raw : log1pf(__expf(c_raw));
            g_p2[(a0h + a) * 4 + 3] = sqrtf(sp);
        }
    }

    // mu[d] = h1[atom,d,:] . muW  -- 96 rows, 16 warps -> 6 rows each,
    // loads batched then 6 interleaved shuffle chains
    float mw0 = muW[lane], mw1 = muW[lane + 32];
    float mw2 = muW[lane + 64], mw3 = muW[lane + 96];
    float vv[6];
    #pragma unroll
    for (int kk = 0; kk < 6; kk++) {
        int r = warp + 16 * kk;
        const float* row = h1 + ((size_t)a0 * 3 + r) * FDIM;
        vv[kk] = row[lane] * mw0 + row[lane + 32] * mw1
               + row[lane + 64] * mw2 + row[lane + 96] * mw3;
    }
    #pragma unroll
    for (int off = 16; off >= 1; off >>= 1) {
        #pragma unroll
        for (int kk = 0; kk < 6; kk++)
            vv[kk] += __shfl_xor_sync(0xffffffffu, vv[kk], off);
    }
    if (lane == 0) {
        #pragma unroll
        for (int kk = 0; kk < 6; kk++) {
            int r = warp + 16 * kk;
            g_p2[(a0 + r / 3) * 4 + (r % 3)] = vv[kk];
        }
    }
}

// ================= pairwise energy (exact R9 best) ==========================
// 128 threads. SPLIT blocks per molecule; warp owns rows i (boustrophedon),
// lanes stride over j > i.
__global__ __launch_bounds__(128) void pair_kernel(float* __restrict__ out)
{
    int b     = blockIdx.x / SPLIT;
    int slice = blockIdx.x % SPLIT;
    int t     = threadIdx.x;
    int warp  = t >> 5, lane = t & 31;

    __shared__ float4 sA[MAXSEG];   // {x, y, z, (q - qmean)*QSCALE}
    __shared__ float4 sB[MAXSEG];   // {mux, muy, muz, sqrt_c6}
    __shared__ float  wred[4];
    __shared__ float  s_qmeanS;

    int s = g_start[b];
    int e = g_end[b];
    int m = e - s;
    if (m > MAXSEG) m = MAXSEG;

    float accE = 0.0f;
    if (m > 0) {
        for (int k = t; k < m; k += 128) {
            sA[k] = ((const float4*)g_p1)[s + k];
            sB[k] = ((const float4*)g_p2)[s + k];
        }
        __syncthreads();

        // scaled q mean over segment
        float ls = 0.0f;
        for (int k = t; k < m; k += 128) ls += sA[k].w;
        #pragma unroll
        for (int off = 16; off >= 1; off >>= 1)
            ls += __shfl_xor_sync(0xffffffffu, ls, off);
        if (lane == 0) wred[warp] = ls;
        __syncthreads();
        if (t == 0)
            s_qmeanS = (wred[0] + wred[1] + wred[2] + wred[3]) / (float)m;
        __syncthreads();
        float qmeanS = s_qmeanS;
        for (int k = t; k < m; k += 128) sA[k].w -= qmeanS;
        __syncthreads();

        const int W = SPLIT * 4;             // 128 warps per molecule
        int wm = slice * 4 + warp;

        for (int k = 0; k * W < m; k++) {
            int i = (k & 1) ? ((k + 1) * W - 1 - wm) : (k * W + wm);
            if (i >= m - 1) continue;
            float4 Ai = sA[i];
            float4 Bi = sB[i];

            #pragma unroll 2
            for (int j = i + 1 + lane; j < m; j += 32) {
                float4 Aj = sA[j];
                float4 Bj = sB[j];
                float dx = Ai.x - Aj.x;
                float dy = Ai.y - Aj.y;
                float dz = Ai.z - Aj.z;
                float d2 = fmaf(dx, dx, fmaf(dy, dy, dz * dz));
                float d2e = d2 + 1e-8f;
                float invd = rsqrtf(d2e);
                float dist = d2e * invd;

                // Coulomb (sqrt(14.399) folded into both q's)
                float taper = 1.0f - __expf(-0.5f * dist);
                float ev = Ai.w * Aj.w * invd * taper;

                // vdW
                float r6 = d2 * d2 * d2;
                ev -= __fdividef(Bi.w * Bj.w, r6 + 20.0f);

                // dipole-dipole
                float mm  = Bi.x * Bj.x + Bi.y * Bj.y + Bi.z * Bj.z;
                float mdi = Bi.x * dx + Bi.y * dy + Bi.z * dz;
                float mdj = Bj.x * dx + Bj.y * dy + Bj.z * dz;
                float num = mm - 3.0f * mdi * mdj * invd * invd;
                ev += __fdividef(num, d2 * dist + 10.0f);

                accE += ev;
            }
        }
    }

    // block reduce
    #pragma unroll
    for (int off = 16; off >= 1; off >>= 1)
        accE += __shfl_xor_sync(0xffffffffu, accE, off);
    __syncthreads();
    if (lane == 0) wred[warp] = accE;
    __syncthreads();

    if (t == 0) {
        atomicAdd(&g_energy, (double)(wred[0] + wred[1] + wred[2] + wred[3]));
        __threadfence();
        int done = atomicAdd(&g_done, 1);
        if (done == (int)gridDim.x - 1)
            out[0] = (float)g_energy;
    }
}

// ---------------- launch ----------------
extern "C" void kernel_launch(void* const* d_in, const int* in_sizes, int n_in,
                              void* d_out, int out_size)
{
    const float* h0    = (const float*)d_in[0];
    const float* h1    = (const float*)d_in[1];
    const float* pos   = (const float*)d_in[2];
    const int*   batch = (const int*)  d_in[3];
    const float* qW1   = (const float*)d_in[4];
    const float* qb1   = (const float*)d_in[5];
    const float* qW2   = (const float*)d_in[6];
    const float* qb2   = (const float*)d_in[7];
    const float* cW1   = (const float*)d_in[8];
    const float* cb1   = (const float*)d_in[9];
    const float* cW2   = (const float*)d_in[10];
    const float* cb2   = (const float*)d_in[11];
    const float* muW   = (const float*)d_in[12];

    int N = in_sizes[3];

    features_kernel<<<N / TA, 512>>>(h0, h1, pos, batch, qW1, qb1, qW2, qb2,
                                     cW1, cb1, cW2, cb2, muW, N);
    pair_kernel<<<NB * SPLIT, 128>>>((float*)d_out);
}

// round 15
// speedup vs baseline: 1.1761x; 1.1761x over previous
#include <cuda_runtime.h>
#include <cuda_bf16.h>
#include <math.h>

#define MAXN   8192
#define FDIM   128
#define HDIM   64
#define NB     48
#define TA     16        // atoms per feature block (two 8-atom halves)
#define MAXSEG 320       // max atoms per molecule (mean 128, sd ~11)
#define SPLIT  32        // blocks per molecule in pair kernel
#define QSCALE 3.7946016f   // sqrt(14.399)

// ---------------- device scratch (zero-init; reset by features blk 0) -------
__device__ double g_energy;
__device__ int    g_done;
__device__ int    g_start[NB];
__device__ int    g_end[NB];
__device__ __align__(16) float g_p1[MAXN * 4];   // {x, y, z, q*QSCALE}
__device__ __align__(16) float g_p2[MAXN * 4];   // {mux, muy, muz, sqrt_c6}

// ---------------- f32x2 helpers ---------------------------------------------
__device__ __forceinline__ unsigned long long pack2(float lo, float hi) {
    unsigned long long r;
    asm("mov.b64 %0, {%1, %2};" : "=l"(r) : "f"(lo), "f"(hi));
    return r;
}
__device__ __forceinline__ void unpack2(unsigned long long v, float& lo, float& hi) {
    asm("mov.b64 {%0, %1}, %2;" : "=f"(lo), "=f"(hi) : "l"(v));
}
__device__ __forceinline__ void ffma2(unsigned long long& d, unsigned long long a,
                                      unsigned long long b, unsigned long long c) {
    asm("fma.rn.f32x2 %0, %1, %2, %3;" : "=l"(d) : "l"(a), "l"(b), "l"(c));
}
__device__ __forceinline__ void lds_v2_u64(unsigned long long& a, unsigned long long& b,
                                           unsigned int smem_addr) {
    asm("ld.shared.v2.u64 {%0, %1}, [%2];" : "=l"(a), "=l"(b) : "r"(smem_addr));
}

// ================= features =================================================
// 256 threads = two independent 128-thread halves; each half: 8 atoms,
// thread ht: hidden unit ht&63 of MLP ht>>6. Weight loads software-pipelined
// one f0-iteration ahead.
__global__ __launch_bounds__(256) void features_kernel(
    const float* __restrict__ h0, const float* __restrict__ h1,
    const float* __restrict__ pos, const int* __restrict__ batch,
    const float* __restrict__ qW1, const float* __restrict__ qb1,
    const float* __restrict__ qW2, const float* __restrict__ qb2,
    const float* __restrict__ cW1, const float* __restrict__ cb1,
    const float* __restrict__ cW2, const float* __restrict__ cb2,
    const float* __restrict__ muW, int N)
{
    int t    = threadIdx.x;          // 0..255
    int half = t >> 7;               // 0 or 1
    int ht   = t & 127;
    int a0   = blockIdx.x * TA;      // block's first atom
    int a0h  = a0 + half * 8;        // this half's first atom

    if (blockIdx.x == 0 && t == 0) { g_energy = 0.0; g_done = 0; }

    __shared__ __align__(16) float h0s[TA][FDIM];    // 8 KB
    __shared__ float part[8][8];                     // [warp][atom-in-half]

    int warp = t >> 5, lane = t & 31;

    // prefetch pos for this half's atom ht (same thread writes g_p1 later)
    float px = 0.f, py = 0.f, pz = 0.f;
    if (ht < 8) {
        px = pos[(a0h + ht) * 3 + 0];
        py = pos[(a0h + ht) * 3 + 1];
        pz = pos[(a0h + ht) * 3 + 2];
    }

    // stage h0 tile: 512 float4, 256 threads -> 2 each (coalesced)
    {
        const float4* src = (const float4*)(h0 + (size_t)a0 * FDIM);
        float4* dst = (float4*)&h0s[0][0];
        dst[t]       = src[t];
        dst[t + 256] = src[t + 256];
    }

    // segment boundary detection (batch is sorted)
    if (t < TA) {
        int i  = a0 + t;
        int bi = batch[i];
        if (i == 0 || batch[i - 1] != bi) g_start[bi] = i;
        if (i == N - 1 || batch[i + 1] != bi) g_end[bi] = i + 1;
    }
    __syncthreads();

    int mlp = ht >> 6;          // 0 = q, 1 = c
    int hu  = ht & 63;
    const float* W1 = mlp ? cW1 : qW1;
    const float* B1 = mlp ? cb1 : qb1;
    const float* W2 = mlp ? cW2 : qW2;

    unsigned int hbase = (unsigned int)__cvta_generic_to_shared(&h0s[0][0])
                       + half * 8 * (FDIM * 4);

    unsigned long long acc[8];
    #pragma unroll
    for (int a = 0; a < 8; a++) acc[a] = 0ull;

    // software-pipelined weight loads: iteration f0 consumes weights loaded
    // one iteration earlier; loads lead their use by a full atom sweep.
    const float* wp0 = W1 + hu;
    float wa = wp0[0];
    float wb = wp0[HDIM];
    float wc = wp0[2 * HDIM];
    float wd = wp0[3 * HDIM];

    #pragma unroll 4
    for (int f0 = 0; f0 < FDIM; f0 += 4) {
        // issue NEXT iteration's loads first
        float na = 0.f, nb = 0.f, nc = 0.f, nd = 0.f;
        if (f0 + 4 < FDIM) {
            const float* wp = W1 + (f0 + 4) * HDIM + hu;
            na = wp[0];
            nb = wp[HDIM];
            nc = wp[2 * HDIM];
            nd = wp[3 * HDIM];
        }

        unsigned long long w01 = pack2(wa, wb);
        unsigned long long w23 = pack2(wc, wd);
        unsigned int addr = hbase + f0 * 4;
        #pragma unroll
        for (int a = 0; a < 8; a++) {
            unsigned long long hA, hB;
            lds_v2_u64(hA, hB, addr + a * (FDIM * 4));   // uniform -> broadcast
            ffma2(acc[a], hA, w01, acc[a]);
            ffma2(acc[a], hB, w23, acc[a]);
        }

        wa = na; wb = nb; wc = nc; wd = nd;
    }

    // epilogue: silu * W2, then 8 INTERLEAVED shuffle-reduce chains
    float b1v = B1[hu];
    float w2v = W2[hu];
    float v[8];
    #pragma unroll
    for (int a = 0; a < 8; a++) {
        float p0, p1;
        unpack2(acc[a], p0, p1);
        float pre = p0 + p1 + b1v;
        v[a] = (pre / (1.0f + __expf(-pre))) * w2v;
    }
    #pragma unroll
    for (int off = 16; off >= 1; off >>= 1) {
        #pragma unroll
        for (int a = 0; a < 8; a++)
            v[a] += __shfl_xor_sync(0xffffffffu, v[a], off);
    }
    if (lane == 0) {
        #pragma unroll
        for (int a = 0; a < 8; a++) part[warp][a] = v[a];
    }
    __syncthreads();

    if (ht < 16) {
        int m2 = ht >> 3, a = ht & 7;    // m2: 0=q, 1=c
        float sum = part[half * 4 + 2 * m2][a] + part[half * 4 + 2 * m2 + 1][a];
        if (m2 == 0) {
            // ht == a here, so px/py/pz belong to atom a0h + a
            float qs = (sum + qb2[0]) * QSCALE;
            ((float4*)g_p1)[a0h + a] = make_float4(px, py, pz, qs);
        } else {
            float c_raw = sum + cb2[0];
            float sp = (c_raw > 20.0f) ? c_raw : log1pf(__expf(c_raw));
            g_p2[(a0h + a) * 4 + 3] = sqrtf(sp);
        }
    }

    // mu[d] = h1[atom,d,:] . muW  -- 48 rows, 8 warps -> 6 rows each, batched
    float mw0 = muW[lane], mw1 = muW[lane + 32];
    float mw2 = muW[lane + 64], mw3 = muW[lane + 96];
    float vv[6];
    #pragma unroll
    for (int kk = 0; kk < 6; kk++) {
        int r = warp + 8 * kk;
        const float* row = h1 + ((size_t)a0 * 3 + r) * FDIM;
        vv[kk] = row[lane] * mw0 + row[lane + 32] * mw1
               + row[lane + 64] * mw2 + row[lane + 96] * mw3;
    }
    #pragma unroll
    for (int off = 16; off >= 1; off >>= 1) {
        #pragma unroll
        for (int kk = 0; kk < 6; kk++)
            vv[kk] += __shfl_xor_sync(0xffffffffu, vv[kk], off);
    }
    if (lane == 0) {
        #pragma unroll
        for (int kk = 0; kk < 6; kk++) {
            int r = warp + 8 * kk;
            g_p2[(a0 + r / 3) * 4 + (r % 3)] = vv[kk];
        }
    }
}

// ================= pairwise energy ==========================================
// 128 threads. SPLIT blocks per molecule; warp owns rows i (boustrophedon),
// lanes stride over j > i. Single-sync qmean (computed during staging,
// subtracted in registers).
__global__ __launch_bounds__(128) void pair_kernel(float* __restrict__ out)
{
    int b     = blockIdx.x / SPLIT;
    int slice = blockIdx.x % SPLIT;
    int t     = threadIdx.x;
    int warp  = t >> 5, lane = t & 31;

    __shared__ float4 sA[MAXSEG];   // {x, y, z, q*QSCALE}
    __shared__ float4 sB[MAXSEG];   // {mux, muy, muz, sqrt_c6}
    __shared__ float  wred[4];

    int s = g_start[b];
    int e = g_end[b];
    int m = e - s;
    if (m > MAXSEG) m = MAXSEG;

    float accE = 0.0f;
    if (m > 0) {
        // stage + accumulate q-sum in one pass
        float ls = 0.0f;
        for (int k = t; k < m; k += 128) {
            float4 A = ((const float4*)g_p1)[s + k];
            sA[k] = A;
            ls += A.w;
            sB[k] = ((const float4*)g_p2)[s + k];
        }
        #pragma unroll
        for (int off = 16; off >= 1; off >>= 1)
            ls += __shfl_xor_sync(0xffffffffu, ls, off);
        if (lane == 0) wred[warp] = ls;
        __syncthreads();                       // single barrier

        float qm = (wred[0] + wred[1] + wred[2] + wred[3]) / (float)m;

        const int W = SPLIT * 4;             // 128 warps per molecule
        int wm = slice * 4 + warp;

        for (int k = 0; k * W < m; k++) {
            int i = (k & 1) ? ((k + 1) * W - 1 - wm) : (k * W + wm);
            if (i >= m - 1) continue;
            float4 Ai = sA[i];
            float4 Bi = sB[i];
            float qAi = Ai.w - qm;             // once per row

            #pragma unroll 2
            for (int j = i + 1 + lane; j < m; j += 32) {
                float4 Aj = sA[j];
                float4 Bj = sB[j];
                float dx = Ai.x - Aj.x;
                float dy = Ai.y - Aj.y;
                float dz = Ai.z - Aj.z;
                float d2 = fmaf(dx, dx, fmaf(dy, dy, dz * dz));
                float d2e = d2 + 1e-8f;
                float invd = rsqrtf(d2e);
                float dist = d2e * invd;

                // Coulomb (sqrt(14.399) folded into both q's)
                float taper = 1.0f - __expf(-0.5f * dist);
                float ev = qAi * (Aj.w - qm) * invd * taper;

                // vdW
                float r6 = d2 * d2 * d2;
                ev -= __fdividef(Bi.w * Bj.w, r6 + 20.0f);

                // dipole-dipole
                float mm  = Bi.x * Bj.x + Bi.y * Bj.y + Bi.z * Bj.z;
                float mdi = Bi.x * dx + Bi.y * dy + Bi.z * dz;
                float mdj = Bj.x * dx + Bj.y * dy + Bj.z * dz;
                float num = mm - 3.0f * mdi * mdj * invd * invd;
                ev += __fdividef(num, d2 * dist + 10.0f);

                accE += ev;
            }
        }
    }

    // block reduce
    #pragma unroll
    for (int off = 16; off >= 1; off >>= 1)
        accE += __shfl_xor_sync(0xffffffffu, accE, off);
    __syncthreads();
    if (lane == 0) wred[warp] = accE;
    __syncthreads();

    if (t == 0) {
        atomicAdd(&g_energy, (double)(wred[0] + wred[1] + wred[2] + wred[3]));
        __threadfence();
        int done = atomicAdd(&g_done, 1);
        if (done == (int)gridDim.x - 1)
            out[0] = (float)g_energy;
    }
}

// ---------------- launch ----------------
extern "C" void kernel_launch(void* const* d_in, const int* in_sizes, int n_in,
                              void* d_out, int out_size)
{
    const float* h0    = (const float*)d_in[0];
    const float* h1    = (const float*)d_in[1];
    const float* pos   = (const float*)d_in[2];
    const int*   batch = (const int*)  d_in[3];
    const float* qW1   = (const float*)d_in[4];
    const float* qb1   = (const float*)d_in[5];
    const float* qW2   = (const float*)d_in[6];
    const float* qb2   = (const float*)d_in[7];
    const float* cW1   = (const float*)d_in[8];
    const float* cb1   = (const float*)d_in[9];
    const float* cW2   = (const float*)d_in[10];
    const float* cb2   = (const float*)d_in[11];
    const float* muW   = (const float*)d_in[12];

    int N = in_sizes[3];

    features_kernel<<<N / TA, 256>>>(h0, h1, pos, batch, qW1, qb1, qW2, qb2,
                                     cW1, cb1, cW2, cb2, muW, N);
    pair_kernel<<<NB * SPLIT, 128>>>((float*)d_out);
}